// round 1
// baseline (speedup 1.0000x reference)
#include <cuda_runtime.h>
#include <cuda_bf16.h>
#include <math.h>

// Problem constants
#define NN    16384      // total nodes
#define EE    131072     // total edges
#define HH    256        // hidden
#define LL    4          // GAT layers
#define BB    256        // graphs
#define NPG   64         // nodes per graph
#define DEG   8          // out-degree
#define HEADS 8
#define DK    32

// ---------------- scratch (device globals; no allocation allowed) ----------
__device__ float gbuf_h   [NN * HH];      // node state
__device__ float gbuf_m   [NN * HH];      // GAT m / FF y2 / gating t
__device__ float gbuf_q   [NN * HH];
__device__ float gbuf_k   [NN * HH];
__device__ float gbuf_v   [NN * HH];
__device__ float gbuf_att [NN * HH];
__device__ float gbuf_x   [NN * HH];      // post-attention x
__device__ float gbuf_y1  [NN * 2 * HH];  // FF hidden
__device__ float gbuf_elog[LL * EE];      // per-layer edge logits
__device__ float gbuf_we  [LL * 32];      // folded We @ a_e
__device__ float gbuf_ce  [LL];           // folded be . a_e
__device__ float gbuf_gs  [NN];           // gating scalars

// ---------------- fold edge weights:  we[l] = We @ a_e[l], ce[l]=be.a_e[l] --
__global__ void prep_kernel(const float* __restrict__ We, const float* __restrict__ be,
                            const float* __restrict__ gat_a,
                            float* __restrict__ we, float* __restrict__ ce)
{
    int tid = threadIdx.x;
    if (tid < 128) {
        int l = tid / 32, j = tid % 32;
        const float* ae = gat_a + l * 768 + 512;
        float s = 0.f;
        for (int c = 0; c < HH; c++) s += We[j * HH + c] * ae[c];
        we[tid] = s;
    } else if (tid < 132) {
        int l = tid - 128;
        const float* ae = gat_a + l * 768 + 512;
        float s = 0.f;
        for (int c = 0; c < HH; c++) s += be[c] * ae[c];
        ce[l] = s;
    }
}

// ---------------- edge logits for all 4 layers ------------------------------
__global__ void edge_logit_kernel(const float* __restrict__ ef,
                                  const float* __restrict__ we,
                                  const float* __restrict__ ce,
                                  float* __restrict__ elog)
{
    __shared__ float ws[128];
    __shared__ float cs[4];
    int tid = threadIdx.x;
    if (tid < 128) ws[tid] = we[tid];
    if (tid < 4)   cs[tid] = ce[tid];
    __syncthreads();
    int e = blockIdx.x * 256 + tid;
    float f[32];
    const float4* efp = reinterpret_cast<const float4*>(ef + (long)e * 32);
#pragma unroll
    for (int t = 0; t < 8; t++) {
        float4 x = efp[t];
        f[4*t+0] = x.x; f[4*t+1] = x.y; f[4*t+2] = x.z; f[4*t+3] = x.w;
    }
#pragma unroll
    for (int l = 0; l < LL; l++) {
        float s = cs[l];
#pragma unroll
        for (int j = 0; j < 32; j++) s += f[j] * ws[l * 32 + j];
        elog[l * EE + e] = s;
    }
}

// ---------------- SGEMM: C[M,Nc] = A[M,K] @ W[K,Nc] (+bias)(+act) ----------
// BM=128 BN=128 BK=16, 256 threads, 8x8 microtile. All dims divide tiles.
// ACT: 0 none, 1 exact GELU, 2 ReLU
template<int ACT>
__global__ __launch_bounds__(256)
void sgemm_kernel(int M, int Nc, int K,
                  const float* __restrict__ A, const float* __restrict__ W,
                  const float* __restrict__ bias, float* __restrict__ C)
{
    const int BM = 128, BN = 128, BK = 16, TM = 8, TN = 8;
    __shared__ float As[BK][BM];
    __shared__ float Bs[BK][BN];
    int tid = threadIdx.x;
    int bm = blockIdx.y * BM;
    int bn = blockIdx.x * BN;
    int tx = tid % 16, ty = tid / 16;
    float acc[TM][TN];
#pragma unroll
    for (int i = 0; i < TM; i++)
#pragma unroll
        for (int j = 0; j < TN; j++) acc[i][j] = 0.f;

    int aRow = tid / 4;          // 0..63
    int aCol = (tid % 4) * 4;    // 0,4,8,12
    int bRow = tid / 32;         // 0..7
    int bCol = (tid % 32) * 4;   // 0..124

    for (int k0 = 0; k0 < K; k0 += BK) {
#pragma unroll
        for (int i = 0; i < 2; i++) {
            float4 t = *reinterpret_cast<const float4*>(
                &A[(long)(bm + aRow + i * 64) * K + k0 + aCol]);
            As[aCol + 0][aRow + i * 64] = t.x;
            As[aCol + 1][aRow + i * 64] = t.y;
            As[aCol + 2][aRow + i * 64] = t.z;
            As[aCol + 3][aRow + i * 64] = t.w;
        }
#pragma unroll
        for (int i = 0; i < 2; i++) {
            float4 t = *reinterpret_cast<const float4*>(
                &W[(long)(k0 + bRow + i * 8) * Nc + bn + bCol]);
            *reinterpret_cast<float4*>(&Bs[bRow + i * 8][bCol]) = t;
        }
        __syncthreads();
        float regM[TM], regN[TN];
#pragma unroll
        for (int k = 0; k < BK; k++) {
#pragma unroll
            for (int i = 0; i < TM; i++) regM[i] = As[k][ty * TM + i];
#pragma unroll
            for (int j = 0; j < TN; j++) regN[j] = Bs[k][tx * TN + j];
#pragma unroll
            for (int i = 0; i < TM; i++)
#pragma unroll
                for (int j = 0; j < TN; j++)
                    acc[i][j] += regM[i] * regN[j];
        }
        __syncthreads();
    }

#pragma unroll
    for (int i = 0; i < TM; i++) {
        long row = bm + ty * TM + i;
#pragma unroll
        for (int j = 0; j < TN; j++) {
            int col = bn + tx * TN + j;
            float vv = acc[i][j];
            if (bias) vv += bias[col];
            if (ACT == 1) vv = 0.5f * vv * (1.0f + erff(vv * 0.7071067811865475f));
            if (ACT == 2) vv = fmaxf(vv, 0.0f);
            C[row * Nc + col] = vv;
        }
    }
}

// ---------------- GAT layer: logits/softmax/aggregate/residual/LN ----------
// one block per graph, 256 threads = 8 warps, warp handles 8 nodes.
__global__ __launch_bounds__(256)
void gat_kernel(const float* __restrict__ m, float* __restrict__ h,
                const float* __restrict__ elog_l, const int* __restrict__ dst,
                const float* __restrict__ a_l,   // 768, [0:256)=a_i [256:512)=a_j
                const float* __restrict__ lng, const float* __restrict__ lnb)
{
    int g = blockIdx.x;
    int tid = threadIdx.x;
    int w = tid >> 5, lane = tid & 31;
    __shared__ float ai[NPG], aj[NPG];
    __shared__ float s_attn[8][8];
    __shared__ int   s_dl[8][8];

    // phase 1: per-node alphas
    for (int n = w; n < NPG; n += 8) {
        long row = (long)(g * NPG + n) * HH;
        float si = 0.f, sj = 0.f;
        for (int c = lane; c < HH; c += 32) {
            float mv = m[row + c];
            si += mv * a_l[c];
            sj += mv * a_l[HH + c];
        }
#pragma unroll
        for (int o = 16; o; o >>= 1) {
            si += __shfl_xor_sync(0xFFFFFFFFu, si, o);
            sj += __shfl_xor_sync(0xFFFFFFFFu, sj, o);
        }
        if (lane == 0) { ai[n] = si; aj[n] = sj; }
    }
    __syncthreads();

    // phase 2: per node — softmax over its 8 edges, aggregate, residual+LN
    for (int n = w; n < NPG; n += 8) {
        int node = g * NPG + n;
        float logit = -1e30f;
        int dl = 0;
        if (lane < DEG) {
            int e = node * DEG + lane;
            dl = dst[e] - g * NPG;
            float lg = ai[n] + aj[dl] + elog_l[e];
            logit = (lg >= 0.f) ? lg : 0.01f * lg;
        }
        float mx = logit;
#pragma unroll
        for (int o = 4; o; o >>= 1) mx = fmaxf(mx, __shfl_xor_sync(0xFFFFFFFFu, mx, o));
        float ex = (lane < DEG) ? expf(logit - mx) : 0.f;
        float sm = ex;
#pragma unroll
        for (int o = 4; o; o >>= 1) sm += __shfl_xor_sync(0xFFFFFFFFu, sm, o);
        if (lane < DEG) { s_attn[w][lane] = ex / sm; s_dl[w][lane] = dl; }
        __syncwarp();

        float acc[8];
#pragma unroll
        for (int jj = 0; jj < 8; jj++) acc[jj] = 0.f;
        long gbase = (long)g * NPG * HH;
#pragma unroll
        for (int kk = 0; kk < DEG; kk++) {
            float at = s_attn[w][kk];
            const float* mr = m + gbase + (long)s_dl[w][kk] * HH;
#pragma unroll
            for (int jj = 0; jj < 8; jj++)
                acc[jj] += at * mr[lane + 32 * jj];
        }
        // residual + LN (eps 1e-5)
        float* hr = h + (long)node * HH;
        float s = 0.f, s2 = 0.f;
#pragma unroll
        for (int jj = 0; jj < 8; jj++) {
            float vv = acc[jj] + hr[lane + 32 * jj];
            acc[jj] = vv;
            s += vv; s2 += vv * vv;
        }
#pragma unroll
        for (int o = 16; o; o >>= 1) {
            s  += __shfl_xor_sync(0xFFFFFFFFu, s,  o);
            s2 += __shfl_xor_sync(0xFFFFFFFFu, s2, o);
        }
        float mean = s * (1.0f / HH);
        float var  = s2 * (1.0f / HH) - mean * mean;
        float inv  = rsqrtf(var + 1e-5f);
#pragma unroll
        for (int jj = 0; jj < 8; jj++) {
            int c = lane + 32 * jj;
            hr[c] = (acc[jj] - mean) * inv * lng[c] + lnb[c];
        }
        __syncwarp();
    }
}

// ---------------- global attention: block per (graph, head), 64 threads ----
__global__ __launch_bounds__(64)
void attn_kernel(const float* __restrict__ q, const float* __restrict__ k,
                 const float* __restrict__ v, float* __restrict__ o)
{
    int g = blockIdx.x, hd = blockIdx.y;
    int i = threadIdx.x;   // query row
    __shared__ float ks[NPG][DK];
    __shared__ float vs[NPG][DK];
    __shared__ float sc[NPG][NPG + 1];
    long base = (long)g * NPG * HH + hd * DK;
    for (int t = i; t < NPG * DK; t += 64) {
        int r = t / DK, c = t % DK;
        ks[r][c] = k[base + (long)r * HH + c];
        vs[r][c] = v[base + (long)r * HH + c];
    }
    __syncthreads();
    float qr[DK];
#pragma unroll
    for (int d = 0; d < DK; d++) qr[d] = q[base + (long)i * HH + d];
    float mx = -1e30f;
    for (int j = 0; j < NPG; j++) {
        float s = 0.f;
#pragma unroll
        for (int d = 0; d < DK; d++) s += qr[d] * ks[j][d];
        s *= 0.1767766952966369f;   // 1/sqrt(32)
        sc[i][j] = s;
        mx = fmaxf(mx, s);
    }
    float sm = 0.f;
    for (int j = 0; j < NPG; j++) {
        float e = expf(sc[i][j] - mx);
        sc[i][j] = e;
        sm += e;
    }
    float inv = 1.0f / sm;
#pragma unroll 4
    for (int d = 0; d < DK; d++) {
        float acc = 0.f;
        for (int j = 0; j < NPG; j++) acc += sc[i][j] * vs[j][d];
        o[base + (long)i * HH + d] = acc * inv;
    }
}

// ---------------- out = LN(a + b) ------------------------------------------
__global__ __launch_bounds__(256)
void add_ln_kernel(const float* __restrict__ a, const float* __restrict__ b,
                   const float* __restrict__ gamma, const float* __restrict__ beta,
                   float eps, float* __restrict__ out)
{
    long r = blockIdx.x;
    int c = threadIdx.x;
    int w = c >> 5, lane = c & 31;
    float vv = a[r * HH + c] + b[r * HH + c];
    float s = vv, s2 = vv * vv;
#pragma unroll
    for (int o = 16; o; o >>= 1) {
        s  += __shfl_xor_sync(0xFFFFFFFFu, s,  o);
        s2 += __shfl_xor_sync(0xFFFFFFFFu, s2, o);
    }
    __shared__ float rs[8], rs2[8];
    if (lane == 0) { rs[w] = s; rs2[w] = s2; }
    __syncthreads();
    float ts = 0.f, ts2 = 0.f;
#pragma unroll
    for (int i = 0; i < 8; i++) { ts += rs[i]; ts2 += rs2[i]; }
    float mean = ts * (1.0f / HH);
    float var  = ts2 * (1.0f / HH) - mean * mean;
    float inv  = rsqrtf(var + eps);
    out[r * HH + c] = (vv - mean) * inv * gamma[c] + beta[c];
}

// ---------------- gating scalar: gs[n] = relu_t[n] . w2 + b2 ---------------
__global__ __launch_bounds__(256)
void rowdot_kernel(const float* __restrict__ t, const float* __restrict__ w2,
                   const float* __restrict__ b2, float* __restrict__ gs)
{
    int w = threadIdx.x >> 5, lane = threadIdx.x & 31;
    long r = (long)blockIdx.x * 8 + w;
    float s = 0.f;
    for (int c = lane; c < HH; c += 32) s += t[r * HH + c] * w2[c];
#pragma unroll
    for (int o = 16; o; o >>= 1) s += __shfl_xor_sync(0xFFFFFFFFu, s, o);
    if (lane == 0) gs[r] = s + b2[0];
}

// ---------------- readout: per-graph softmax-weighted sum ------------------
__global__ __launch_bounds__(256)
void readout_kernel(const float* __restrict__ x, const float* __restrict__ gs,
                    float* __restrict__ out)
{
    int g = blockIdx.x, tid = threadIdx.x;
    __shared__ float p[NPG];
    if (tid < NPG) p[tid] = gs[g * NPG + tid];
    __syncthreads();
    if (tid == 0) {
        float mx = -1e30f;
        for (int i = 0; i < NPG; i++) mx = fmaxf(mx, p[i]);
        float sm = 0.f;
        for (int i = 0; i < NPG; i++) { p[i] = expf(p[i] - mx); sm += p[i]; }
        float inv = 1.0f / sm;
        for (int i = 0; i < NPG; i++) p[i] *= inv;
    }
    __syncthreads();
    float acc = 0.f;
    long gbase = (long)g * NPG * HH;
    for (int n = 0; n < NPG; n++)
        acc += p[n] * x[gbase + (long)n * HH + tid];
    out[(long)g * HH + tid] = acc;
}

// ---------------- launch ----------------------------------------------------
extern "C" void kernel_launch(void* const* d_in, const int* in_sizes, int n_in,
                              void* d_out, int out_size)
{
    const float* node_feats = (const float*)d_in[0];
    const float* edge_feats = (const float*)d_in[1];
    // d_in[2] = src: structurally repeat(arange(N), DEG) -> implicit
    const int*   dst        = (const int*)  d_in[3];
    const float* Wn      = (const float*)d_in[4];
    const float* bn      = (const float*)d_in[5];
    const float* We      = (const float*)d_in[6];
    const float* be      = (const float*)d_in[7];
    const float* gat_W   = (const float*)d_in[8];
    const float* gat_a   = (const float*)d_in[9];
    const float* gat_lng = (const float*)d_in[10];
    const float* gat_lnb = (const float*)d_in[11];
    const float* Wq      = (const float*)d_in[12];
    const float* Wk      = (const float*)d_in[13];
    const float* Wv      = (const float*)d_in[14];
    const float* att_lng = (const float*)d_in[15];
    const float* att_lnb = (const float*)d_in[16];
    const float* ff_W1   = (const float*)d_in[17];
    const float* ff_b1   = (const float*)d_in[18];
    const float* ff_W2   = (const float*)d_in[19];
    const float* ff_b2   = (const float*)d_in[20];
    const float* ff_lng  = (const float*)d_in[21];
    const float* ff_lnb  = (const float*)d_in[22];
    const float* gW1     = (const float*)d_in[23];
    const float* gb1     = (const float*)d_in[24];
    const float* gW2     = (const float*)d_in[25];
    const float* gb2     = (const float*)d_in[26];

    float *h, *m, *q, *k, *v, *att, *x, *y1, *elog, *we, *ce, *gs;
    cudaGetSymbolAddress((void**)&h,    gbuf_h);
    cudaGetSymbolAddress((void**)&m,    gbuf_m);
    cudaGetSymbolAddress((void**)&q,    gbuf_q);
    cudaGetSymbolAddress((void**)&k,    gbuf_k);
    cudaGetSymbolAddress((void**)&v,    gbuf_v);
    cudaGetSymbolAddress((void**)&att,  gbuf_att);
    cudaGetSymbolAddress((void**)&x,    gbuf_x);
    cudaGetSymbolAddress((void**)&y1,   gbuf_y1);
    cudaGetSymbolAddress((void**)&elog, gbuf_elog);
    cudaGetSymbolAddress((void**)&we,   gbuf_we);
    cudaGetSymbolAddress((void**)&ce,   gbuf_ce);
    cudaGetSymbolAddress((void**)&gs,   gbuf_gs);

    dim3 blk(256);
    dim3 grid256(HH / 128, NN / 128);         // Nc=256 GEMMs
    dim3 grid512(2 * HH / 128, NN / 128);     // Nc=512 GEMM

    prep_kernel<<<1, 160>>>(We, be, gat_a, we, ce);
    edge_logit_kernel<<<EE / 256, blk>>>(edge_feats, we, ce, elog);

    // input projection: h = node_feats @ Wn + bn
    sgemm_kernel<0><<<grid256, blk>>>(NN, HH, 64, node_feats, Wn, bn, h);

    // GAT layers
    for (int l = 0; l < LL; l++) {
        sgemm_kernel<0><<<grid256, blk>>>(NN, HH, HH, h, gat_W + (long)l * HH * HH, nullptr, m);
        gat_kernel<<<BB, blk>>>(m, h, elog + (long)l * EE, dst,
                                gat_a + l * 768, gat_lng + l * HH, gat_lnb + l * HH);
    }

    // global attention
    sgemm_kernel<0><<<grid256, blk>>>(NN, HH, HH, h, Wq, nullptr, q);
    sgemm_kernel<0><<<grid256, blk>>>(NN, HH, HH, h, Wk, nullptr, k);
    sgemm_kernel<0><<<grid256, blk>>>(NN, HH, HH, h, Wv, nullptr, v);
    attn_kernel<<<dim3(BB, HEADS), 64>>>(q, k, v, att);
    add_ln_kernel<<<NN, blk>>>(att, h, att_lng, att_lnb, 1e-6f, x);

    // feed-forward
    sgemm_kernel<1><<<grid512, blk>>>(NN, 2 * HH, HH, x, ff_W1, ff_b1, y1);
    sgemm_kernel<0><<<grid256, blk>>>(NN, HH, 2 * HH, y1, ff_W2, ff_b2, m);
    add_ln_kernel<<<NN, blk>>>(x, m, ff_lng, ff_lnb, 1e-6f, h);   // x2 -> h

    // gating readout
    sgemm_kernel<2><<<grid256, blk>>>(NN, HH, HH, h, gW1, gb1, m);
    rowdot_kernel<<<NN / 8, blk>>>(m, gW2, gb2, gs);
    readout_kernel<<<BB, blk>>>(h, gs, (float*)d_out);
}

// round 3
// speedup vs baseline: 1.7662x; 1.7662x over previous
#include <cuda_runtime.h>
#include <cuda_bf16.h>
#include <math.h>
#include <stdint.h>

// Problem constants
#define NN    16384
#define EE    131072
#define HH    256
#define LL    4
#define BB    256
#define NPG   64
#define DEG   8
#define HEADS 8
#define DK    32

// ---------------------------------------------------------------------------
// PTX helpers (baseline PTX only: works on compute_103 virtual arch)
// ---------------------------------------------------------------------------
static __device__ __forceinline__ uint32_t su32(const void* p) {
    uint32_t a;
    asm("{ .reg .u64 t; cvta.to.shared.u64 t, %1; cvt.u32.u64 %0, t; }"
        : "=r"(a) : "l"(p));
    return a;
}
static __device__ __forceinline__ void cp16(uint32_t s, const void* g) {
    asm volatile("cp.async.cg.shared.global [%0], [%1], 16;" :: "r"(s), "l"(g));
}
#define CP_COMMIT() asm volatile("cp.async.commit_group;")
#define CP_WAIT(n)  asm volatile("cp.async.wait_group %0;" :: "n"(n))

static __device__ __forceinline__ void ldm4(uint32_t& r0, uint32_t& r1,
                                            uint32_t& r2, uint32_t& r3, uint32_t a) {
    asm volatile("ldmatrix.sync.aligned.m8n8.x4.shared.b16 {%0,%1,%2,%3}, [%4];"
                 : "=r"(r0), "=r"(r1), "=r"(r2), "=r"(r3) : "r"(a));
}
static __device__ __forceinline__ void mma16816(float* c, const uint32_t* a,
                                                const uint32_t* b) {
    asm volatile("mma.sync.aligned.m16n8k16.row.col.f32.bf16.bf16.f32 "
                 "{%0,%1,%2,%3}, {%4,%5,%6,%7}, {%8,%9}, {%0,%1,%2,%3};"
                 : "+f"(c[0]), "+f"(c[1]), "+f"(c[2]), "+f"(c[3])
                 : "r"(a[0]), "r"(a[1]), "r"(a[2]), "r"(a[3]),
                   "r"(b[0]), "r"(b[1]));
}

// ---------------------------------------------------------------------------
// scratch (device globals)
// ---------------------------------------------------------------------------
__device__ float gbuf_h   [NN * HH];
__device__ float gbuf_m   [NN * HH];
__device__ float gbuf_q   [NN * HH];
__device__ float gbuf_k   [NN * HH];
__device__ float gbuf_v   [NN * HH];
__device__ float gbuf_att [NN * HH];
__device__ float gbuf_x   [NN * HH];
__device__ float gbuf_elog[LL * EE];
__device__ float gbuf_we  [LL * 32];
__device__ float gbuf_ce  [LL];
__device__ float gbuf_gs  [NN];

// bf16 triple buffers: A' = [hi | hi | lo] along K (row-major, 3K contiguous)
//                      B' = [hi | lo | hi] along K
__device__ __nv_bfloat16 b_nf3 [NN * 192];
__device__ __nv_bfloat16 b_h3  [NN * 768];
__device__ __nv_bfloat16 b_x3  [NN * 768];
__device__ __nv_bfloat16 b_h23 [NN * 768];
__device__ __nv_bfloat16 b_y13 [NN * 1536];
__device__ __nv_bfloat16 b_wn3 [256 * 192];
__device__ __nv_bfloat16 b_gat3[4 * 256 * 768];
__device__ __nv_bfloat16 b_wq3 [256 * 768];
__device__ __nv_bfloat16 b_wk3 [256 * 768];
__device__ __nv_bfloat16 b_wv3 [256 * 768];
__device__ __nv_bfloat16 b_w13 [512 * 768];
__device__ __nv_bfloat16 b_w23 [256 * 1536];
__device__ __nv_bfloat16 b_gw13[256 * 768];

static __device__ __forceinline__ void hilo(float v, __nv_bfloat16& h, __nv_bfloat16& l) {
    h = __float2bfloat16(v);
    l = __float2bfloat16(v - __bfloat162float(h));
}

// ---------------------------------------------------------------------------
// conversions
// A-side: src [M,K] row-major -> dst [M,3K] = [hi|hi|lo]
// ---------------------------------------------------------------------------
__global__ void to_tripleA(const float* __restrict__ src, int M, int K,
                           __nv_bfloat16* __restrict__ dst)
{
    long t = (long)blockIdx.x * 256 + threadIdx.x;
    if (t >= (long)M * K) return;
    int r = (int)(t / K), c = (int)(t % K);
    __nv_bfloat16 h, l;
    hilo(src[t], h, l);
    __nv_bfloat16* rp = dst + (size_t)r * 3 * K;
    rp[c] = h; rp[K + c] = h; rp[2 * K + c] = l;
}
// B-side: W [K,Nout] row-major -> dst [Nout,3K] = [hi|lo|hi] (transposed)
__global__ void to_tripleB(const float* __restrict__ W, int K, int Nout,
                           __nv_bfloat16* __restrict__ dst)
{
    long t = (long)blockIdx.x * 256 + threadIdx.x;
    if (t >= (long)K * Nout) return;
    int k = (int)(t / Nout), n = (int)(t % Nout);
    __nv_bfloat16 h, l;
    hilo(W[t], h, l);
    __nv_bfloat16* rp = dst + (size_t)n * 3 * K;
    rp[k] = h; rp[K + k] = l; rp[2 * K + k] = h;
}

// ---------------------------------------------------------------------------
// HMMA GEMM: C[M,NoutT] = A3[M,K3] @ B3[NoutT,K3]^T  (bf16 in, fp32 acc)
// block tile 128x128, 8 warps (4Mx2N), warp tile 32x64, K-chunk 64.
// ACT: 0 none, 1 exact GELU, 2 ReLU. WF32: store fp32 C. WTR: store bf16 triple.
// ---------------------------------------------------------------------------
#define MG_SMEM 65536

template<int ACT, bool WF32, bool WTR>
__global__ __launch_bounds__(256)
void mma_gemm(int KC, int K3,
              const __nv_bfloat16* __restrict__ A3,
              const __nv_bfloat16* __restrict__ B3,
              const float* __restrict__ bias, int NoutT,
              float* __restrict__ C,
              __nv_bfloat16* __restrict__ D3)
{
    extern __shared__ char smem[];
    uint32_t sb = su32(smem);
    int tid = threadIdx.x, lane = tid & 31, wid = tid >> 5;
    int bx = blockIdx.x, by = blockIdx.y;
    const __nv_bfloat16* Abase = A3 + (size_t)by * 128 * K3;
    const __nv_bfloat16* Bbase = B3 + (size_t)bx * 128 * K3;

    float acc[2][8][4];
#pragma unroll
    for (int i = 0; i < 2; i++)
#pragma unroll
        for (int j = 0; j < 8; j++)
#pragma unroll
            for (int q = 0; q < 4; q++) acc[i][j][q] = 0.f;

    auto load_stage = [&](int c) {
        uint32_t st = sb + (uint32_t)(c & 1) * 32768u;
#pragma unroll
        for (int i = 0; i < 4; i++) {
            int idx = tid + i * 256;
            int row = idx >> 3, u = idx & 7;
            uint32_t soff = (uint32_t)row * 128 + (uint32_t)((u ^ (row & 7)) << 4);
            cp16(st + soff,         Abase + (size_t)row * K3 + c * 64 + u * 8);
            cp16(st + 16384 + soff, Bbase + (size_t)row * K3 + c * 64 + u * 8);
        }
    };

    load_stage(0); CP_COMMIT();

    int wm = wid & 3, wn = wid >> 2;
    int g = lane >> 3, r8 = lane & 7;
    int rsel = (g & 1) * 8 + r8;   // row within 16-row tile
    int usel = g >> 1;             // k half (16B unit offset)

    for (int c = 0; c < KC; c++) {
        if (c + 1 < KC) { load_stage(c + 1); CP_COMMIT(); CP_WAIT(1); }
        else            { CP_WAIT(0); }
        __syncthreads();
        uint32_t as = sb + (uint32_t)(c & 1) * 32768u;
        uint32_t bs = as + 16384;
#pragma unroll
        for (int ks = 0; ks < 4; ks++) {
            int u = 2 * ks + usel;
            uint32_t a[2][4];
#pragma unroll
            for (int mt = 0; mt < 2; mt++) {
                int row = wm * 32 + mt * 16 + rsel;
                ldm4(a[mt][0], a[mt][1], a[mt][2], a[mt][3],
                     as + (uint32_t)row * 128 + (uint32_t)((u ^ (row & 7)) << 4));
            }
            uint32_t b[8][2];
#pragma unroll
            for (int np = 0; np < 4; np++) {
                int row = wn * 64 + np * 16 + rsel;
                uint32_t r0, r1, r2, r3;
                ldm4(r0, r1, r2, r3,
                     bs + (uint32_t)row * 128 + (uint32_t)((u ^ (row & 7)) << 4));
                b[2 * np][0] = r0; b[2 * np + 1][0] = r1;
                b[2 * np][1] = r2; b[2 * np + 1][1] = r3;
            }
#pragma unroll
            for (int mt = 0; mt < 2; mt++)
#pragma unroll
                for (int nt = 0; nt < 8; nt++)
                    mma16816(acc[mt][nt], a[mt], b[nt]);
        }
        __syncthreads();
    }

    // epilogue
    int gid = lane >> 2, qp = lane & 3;
#pragma unroll
    for (int mt = 0; mt < 2; mt++) {
#pragma unroll
        for (int nt = 0; nt < 8; nt++) {
            int col = bx * 128 + wn * 64 + nt * 8 + qp * 2;
            float bb0 = bias ? bias[col] : 0.f;
            float bb1 = bias ? bias[col + 1] : 0.f;
#pragma unroll
            for (int hh2 = 0; hh2 < 2; hh2++) {
                long row = (long)by * 128 + wm * 32 + mt * 16 + gid + hh2 * 8;
                float v0 = acc[mt][nt][2 * hh2]     + bb0;
                float v1 = acc[mt][nt][2 * hh2 + 1] + bb1;
                if (ACT == 1) {
                    v0 = 0.5f * v0 * (1.0f + erff(v0 * 0.7071067811865475f));
                    v1 = 0.5f * v1 * (1.0f + erff(v1 * 0.7071067811865475f));
                }
                if (ACT == 2) { v0 = fmaxf(v0, 0.f); v1 = fmaxf(v1, 0.f); }
                if (WF32) {
                    float2 t2 = make_float2(v0, v1);
                    *reinterpret_cast<float2*>(&C[row * NoutT + col]) = t2;
                }
                if (WTR) {
                    __nv_bfloat16 h0, l0, h1, l1;
                    hilo(v0, h0, l0); hilo(v1, h1, l1);
                    __nv_bfloat162 hp, lp;
                    hp.x = h0; hp.y = h1; lp.x = l0; lp.y = l1;
                    __nv_bfloat16* rp = D3 + (size_t)row * 3 * NoutT;
                    *reinterpret_cast<__nv_bfloat162*>(&rp[col]) = hp;
                    *reinterpret_cast<__nv_bfloat162*>(&rp[NoutT + col]) = hp;
                    *reinterpret_cast<__nv_bfloat162*>(&rp[2 * NoutT + col]) = lp;
                }
            }
        }
    }
}

// ---------------------------------------------------------------------------
// fold edge weights
// ---------------------------------------------------------------------------
__global__ void prep_kernel(const float* __restrict__ We, const float* __restrict__ be,
                            const float* __restrict__ gat_a,
                            float* __restrict__ we, float* __restrict__ ce)
{
    int tid = threadIdx.x;
    if (tid < 128) {
        int l = tid / 32, j = tid % 32;
        const float* ae = gat_a + l * 768 + 512;
        float s = 0.f;
        for (int c = 0; c < HH; c++) s += We[j * HH + c] * ae[c];
        we[tid] = s;
    } else if (tid < 132) {
        int l = tid - 128;
        const float* ae = gat_a + l * 768 + 512;
        float s = 0.f;
        for (int c = 0; c < HH; c++) s += be[c] * ae[c];
        ce[l] = s;
    }
}

__global__ void edge_logit_kernel(const float* __restrict__ ef,
                                  const float* __restrict__ we,
                                  const float* __restrict__ ce,
                                  float* __restrict__ elog)
{
    __shared__ float ws[128];
    __shared__ float cs[4];
    int tid = threadIdx.x;
    if (tid < 128) ws[tid] = we[tid];
    if (tid < 4)   cs[tid] = ce[tid];
    __syncthreads();
    int e = blockIdx.x * 256 + tid;
    float f[32];
    const float4* efp = reinterpret_cast<const float4*>(ef + (long)e * 32);
#pragma unroll
    for (int t = 0; t < 8; t++) {
        float4 x = efp[t];
        f[4*t+0] = x.x; f[4*t+1] = x.y; f[4*t+2] = x.z; f[4*t+3] = x.w;
    }
#pragma unroll
    for (int l = 0; l < LL; l++) {
        float s = cs[l];
#pragma unroll
        for (int j = 0; j < 32; j++) s += f[j] * ws[l * 32 + j];
        elog[l * EE + e] = s;
    }
}

// ---------------------------------------------------------------------------
// GAT layer: logits/softmax/aggregate/residual/LN -> h fp32 + h3 triple
// ---------------------------------------------------------------------------
__global__ __launch_bounds__(256)
void gat_kernel(const float* __restrict__ m, float* __restrict__ h,
                const float* __restrict__ elog_l, const int* __restrict__ dst,
                const float* __restrict__ a_l,
                const float* __restrict__ lng, const float* __restrict__ lnb,
                __nv_bfloat16* __restrict__ h3)
{
    int g = blockIdx.x;
    int tid = threadIdx.x;
    int w = tid >> 5, lane = tid & 31;
    __shared__ float ai[NPG], aj[NPG];
    __shared__ float s_attn[8][8];
    __shared__ int   s_dl[8][8];

    for (int n = w; n < NPG; n += 8) {
        long row = (long)(g * NPG + n) * HH;
        float si = 0.f, sj = 0.f;
        for (int c = lane; c < HH; c += 32) {
            float mv = m[row + c];
            si += mv * a_l[c];
            sj += mv * a_l[HH + c];
        }
#pragma unroll
        for (int o = 16; o; o >>= 1) {
            si += __shfl_xor_sync(0xFFFFFFFFu, si, o);
            sj += __shfl_xor_sync(0xFFFFFFFFu, sj, o);
        }
        if (lane == 0) { ai[n] = si; aj[n] = sj; }
    }
    __syncthreads();

    for (int n = w; n < NPG; n += 8) {
        int node = g * NPG + n;
        float logit = -1e30f;
        int dl = 0;
        if (lane < DEG) {
            int e = node * DEG + lane;
            dl = dst[e] - g * NPG;
            float lg = ai[n] + aj[dl] + elog_l[e];
            logit = (lg >= 0.f) ? lg : 0.01f * lg;
        }
        float mx = logit;
#pragma unroll
        for (int o = 4; o; o >>= 1) mx = fmaxf(mx, __shfl_xor_sync(0xFFFFFFFFu, mx, o));
        float ex = (lane < DEG) ? expf(logit - mx) : 0.f;
        float sm = ex;
#pragma unroll
        for (int o = 4; o; o >>= 1) sm += __shfl_xor_sync(0xFFFFFFFFu, sm, o);
        if (lane < DEG) { s_attn[w][lane] = ex / sm; s_dl[w][lane] = dl; }
        __syncwarp();

        float acc[8];
#pragma unroll
        for (int jj = 0; jj < 8; jj++) acc[jj] = 0.f;
        long gbase = (long)g * NPG * HH;
#pragma unroll
        for (int kk = 0; kk < DEG; kk++) {
            float at = s_attn[w][kk];
            const float* mr = m + gbase + (long)s_dl[w][kk] * HH;
#pragma unroll
            for (int jj = 0; jj < 8; jj++)
                acc[jj] += at * mr[lane + 32 * jj];
        }
        float* hr = h + (long)node * HH;
        float s = 0.f, s2 = 0.f;
#pragma unroll
        for (int jj = 0; jj < 8; jj++) {
            float vv = acc[jj] + hr[lane + 32 * jj];
            acc[jj] = vv;
            s += vv; s2 += vv * vv;
        }
#pragma unroll
        for (int o = 16; o; o >>= 1) {
            s  += __shfl_xor_sync(0xFFFFFFFFu, s,  o);
            s2 += __shfl_xor_sync(0xFFFFFFFFu, s2, o);
        }
        float mean = s * (1.0f / HH);
        float var  = s2 * (1.0f / HH) - mean * mean;
        float inv  = rsqrtf(var + 1e-5f);
        __nv_bfloat16* rp = h3 + (size_t)node * 768;
#pragma unroll
        for (int jj = 0; jj < 8; jj++) {
            int c = lane + 32 * jj;
            float val = (acc[jj] - mean) * inv * lng[c] + lnb[c];
            hr[c] = val;
            __nv_bfloat16 hb, lb;
            hilo(val, hb, lb);
            rp[c] = hb; rp[256 + c] = hb; rp[512 + c] = lb;
        }
        __syncwarp();
    }
}

// ---------------------------------------------------------------------------
// global attention
// ---------------------------------------------------------------------------
__global__ __launch_bounds__(64)
void attn_kernel(const float* __restrict__ q, const float* __restrict__ k,
                 const float* __restrict__ v, float* __restrict__ o)
{
    int g = blockIdx.x, hd = blockIdx.y;
    int i = threadIdx.x;
    __shared__ float ks[NPG][DK];
    __shared__ float vs[NPG][DK];
    __shared__ float sc[NPG][NPG + 1];
    long base = (long)g * NPG * HH + hd * DK;
    for (int t = i; t < NPG * DK; t += 64) {
        int r = t / DK, c = t % DK;
        ks[r][c] = k[base + (long)r * HH + c];
        vs[r][c] = v[base + (long)r * HH + c];
    }
    __syncthreads();
    float qr[DK];
#pragma unroll
    for (int d = 0; d < DK; d++) qr[d] = q[base + (long)i * HH + d];
    float mx = -1e30f;
    for (int j = 0; j < NPG; j++) {
        float s = 0.f;
#pragma unroll
        for (int d = 0; d < DK; d++) s += qr[d] * ks[j][d];
        s *= 0.1767766952966369f;
        sc[i][j] = s;
        mx = fmaxf(mx, s);
    }
    float sm = 0.f;
    for (int j = 0; j < NPG; j++) {
        float e = expf(sc[i][j] - mx);
        sc[i][j] = e;
        sm += e;
    }
    float inv = 1.0f / sm;
#pragma unroll 4
    for (int d = 0; d < DK; d++) {
        float acc = 0.f;
        for (int j = 0; j < NPG; j++) acc += sc[i][j] * vs[j][d];
        o[base + (long)i * HH + d] = acc * inv;
    }
}

// ---------------------------------------------------------------------------
// out = LN(a + b) fp32 + optional bf16 triple
// ---------------------------------------------------------------------------
__global__ __launch_bounds__(256)
void add_ln_kernel(const float* __restrict__ a, const float* __restrict__ b,
                   const float* __restrict__ gamma, const float* __restrict__ beta,
                   float eps, float* __restrict__ out,
                   __nv_bfloat16* __restrict__ t3)
{
    long r = blockIdx.x;
    int c = threadIdx.x;
    int w = c >> 5, lane = c & 31;
    float vv = a[r * HH + c] + b[r * HH + c];
    float s = vv, s2 = vv * vv;
#pragma unroll
    for (int o = 16; o; o >>= 1) {
        s  += __shfl_xor_sync(0xFFFFFFFFu, s,  o);
        s2 += __shfl_xor_sync(0xFFFFFFFFu, s2, o);
    }
    __shared__ float rs[8], rs2[8];
    if (lane == 0) { rs[w] = s; rs2[w] = s2; }
    __syncthreads();
    float ts = 0.f, ts2 = 0.f;
#pragma unroll
    for (int i = 0; i < 8; i++) { ts += rs[i]; ts2 += rs2[i]; }
    float mean = ts * (1.0f / HH);
    float var  = ts2 * (1.0f / HH) - mean * mean;
    float inv  = rsqrtf(var + eps);
    float val = (vv - mean) * inv * gamma[c] + beta[c];
    out[r * HH + c] = val;
    if (t3) {
        __nv_bfloat16 hb, lb;
        hilo(val, hb, lb);
        __nv_bfloat16* rp = t3 + (size_t)r * 768;
        rp[c] = hb; rp[256 + c] = hb; rp[512 + c] = lb;
    }
}

// ---------------------------------------------------------------------------
// gating scalar + readout
// ---------------------------------------------------------------------------
__global__ __launch_bounds__(256)
void rowdot_kernel(const float* __restrict__ t, const float* __restrict__ w2,
                   const float* __restrict__ b2, float* __restrict__ gs)
{
    int w = threadIdx.x >> 5, lane = threadIdx.x & 31;
    long r = (long)blockIdx.x * 8 + w;
    float s = 0.f;
    for (int c = lane; c < HH; c += 32) s += t[r * HH + c] * w2[c];
#pragma unroll
    for (int o = 16; o; o >>= 1) s += __shfl_xor_sync(0xFFFFFFFFu, s, o);
    if (lane == 0) gs[r] = s + b2[0];
}

__global__ __launch_bounds__(256)
void readout_kernel(const float* __restrict__ x, const float* __restrict__ gs,
                    float* __restrict__ out)
{
    int g = blockIdx.x, tid = threadIdx.x;
    __shared__ float p[NPG];
    if (tid < NPG) p[tid] = gs[g * NPG + tid];
    __syncthreads();
    if (tid == 0) {
        float mx = -1e30f;
        for (int i = 0; i < NPG; i++) mx = fmaxf(mx, p[i]);
        float sm = 0.f;
        for (int i = 0; i < NPG; i++) { p[i] = expf(p[i] - mx); sm += p[i]; }
        float inv = 1.0f / sm;
        for (int i = 0; i < NPG; i++) p[i] *= inv;
    }
    __syncthreads();
    float acc = 0.f;
    long gbase = (long)g * NPG * HH;
    for (int n = 0; n < NPG; n++)
        acc += p[n] * x[gbase + (long)n * HH + tid];
    out[(long)g * HH + tid] = acc;
}

// ---------------------------------------------------------------------------
// launch
// ---------------------------------------------------------------------------
extern "C" void kernel_launch(void* const* d_in, const int* in_sizes, int n_in,
                              void* d_out, int out_size)
{
    const float* node_feats = (const float*)d_in[0];
    const float* edge_feats = (const float*)d_in[1];
    const int*   dst        = (const int*)  d_in[3];
    const float* Wn      = (const float*)d_in[4];
    const float* bn      = (const float*)d_in[5];
    const float* We      = (const float*)d_in[6];
    const float* be      = (const float*)d_in[7];
    const float* gat_W   = (const float*)d_in[8];
    const float* gat_a   = (const float*)d_in[9];
    const float* gat_lng = (const float*)d_in[10];
    const float* gat_lnb = (const float*)d_in[11];
    const float* Wq      = (const float*)d_in[12];
    const float* Wk      = (const float*)d_in[13];
    const float* Wv      = (const float*)d_in[14];
    const float* att_lng = (const float*)d_in[15];
    const float* att_lnb = (const float*)d_in[16];
    const float* ff_W1   = (const float*)d_in[17];
    const float* ff_b1   = (const float*)d_in[18];
    const float* ff_W2   = (const float*)d_in[19];
    const float* ff_b2   = (const float*)d_in[20];
    const float* ff_lng  = (const float*)d_in[21];
    const float* ff_lnb  = (const float*)d_in[22];
    const float* gW1     = (const float*)d_in[23];
    const float* gb1     = (const float*)d_in[24];
    const float* gW2     = (const float*)d_in[25];
    const float* gb2     = (const float*)d_in[26];

    float *h, *m, *q, *k, *v, *att, *x, *elog, *we, *ce, *gs;
    cudaGetSymbolAddress((void**)&h,    gbuf_h);
    cudaGetSymbolAddress((void**)&m,    gbuf_m);
    cudaGetSymbolAddress((void**)&q,    gbuf_q);
    cudaGetSymbolAddress((void**)&k,    gbuf_k);
    cudaGetSymbolAddress((void**)&v,    gbuf_v);
    cudaGetSymbolAddress((void**)&att,  gbuf_att);
    cudaGetSymbolAddress((void**)&x,    gbuf_x);
    cudaGetSymbolAddress((void**)&elog, gbuf_elog);
    cudaGetSymbolAddress((void**)&we,   gbuf_we);
    cudaGetSymbolAddress((void**)&ce,   gbuf_ce);
    cudaGetSymbolAddress((void**)&gs,   gbuf_gs);

    __nv_bfloat16 *nf3, *h3, *x3, *h23, *y13;
    __nv_bfloat16 *wn3, *gat3, *wq3, *wk3, *wv3, *w13, *w23, *gw13;
    cudaGetSymbolAddress((void**)&nf3,  b_nf3);
    cudaGetSymbolAddress((void**)&h3,   b_h3);
    cudaGetSymbolAddress((void**)&x3,   b_x3);
    cudaGetSymbolAddress((void**)&h23,  b_h23);
    cudaGetSymbolAddress((void**)&y13,  b_y13);
    cudaGetSymbolAddress((void**)&wn3,  b_wn3);
    cudaGetSymbolAddress((void**)&gat3, b_gat3);
    cudaGetSymbolAddress((void**)&wq3,  b_wq3);
    cudaGetSymbolAddress((void**)&wk3,  b_wk3);
    cudaGetSymbolAddress((void**)&wv3,  b_wv3);
    cudaGetSymbolAddress((void**)&w13,  b_w13);
    cudaGetSymbolAddress((void**)&w23,  b_w23);
    cudaGetSymbolAddress((void**)&gw13, b_gw13);

    cudaFuncSetAttribute((const void*)mma_gemm<0, true,  true >, cudaFuncAttributeMaxDynamicSharedMemorySize, MG_SMEM);
    cudaFuncSetAttribute((const void*)mma_gemm<0, true,  false>, cudaFuncAttributeMaxDynamicSharedMemorySize, MG_SMEM);
    cudaFuncSetAttribute((const void*)mma_gemm<1, false, true >, cudaFuncAttributeMaxDynamicSharedMemorySize, MG_SMEM);
    cudaFuncSetAttribute((const void*)mma_gemm<2, true,  false>, cudaFuncAttributeMaxDynamicSharedMemorySize, MG_SMEM);

    dim3 blk(256);

    prep_kernel<<<1, 160>>>(We, be, gat_a, we, ce);
    edge_logit_kernel<<<EE / 256, blk>>>(edge_feats, we, ce, elog);

    // conversions
    to_tripleA<<<(NN * 64 + 255) / 256, blk>>>(node_feats, NN, 64, nf3);
    to_tripleB<<<(64 * 256 + 255) / 256, blk>>>(Wn, 64, 256, wn3);
    for (int l = 0; l < LL; l++)
        to_tripleB<<<(256 * 256 + 255) / 256, blk>>>(gat_W + (long)l * HH * HH, 256, 256,
                                                     gat3 + (size_t)l * 256 * 768);
    to_tripleB<<<(256 * 256 + 255) / 256, blk>>>(Wq, 256, 256, wq3);
    to_tripleB<<<(256 * 256 + 255) / 256, blk>>>(Wk, 256, 256, wk3);
    to_tripleB<<<(256 * 256 + 255) / 256, blk>>>(Wv, 256, 256, wv3);
    to_tripleB<<<(256 * 512 + 255) / 256, blk>>>(ff_W1, 256, 512, w13);
    to_tripleB<<<(512 * 256 + 255) / 256, blk>>>(ff_W2, 512, 256, w23);
    to_tripleB<<<(256 * 256 + 255) / 256, blk>>>(gW1, 256, 256, gw13);

    dim3 g1(2, NN / 128);   // Nout=256
    dim3 g2(4, NN / 128);   // Nout=512

    // input projection: h = nf @ Wn + bn  (fp32 + triple)
    mma_gemm<0, true, true><<<g1, blk, MG_SMEM>>>(3, 192, nf3, wn3, bn, 256, h, h3);

    // GAT layers
    for (int l = 0; l < LL; l++) {
        mma_gemm<0, true, false><<<g1, blk, MG_SMEM>>>(12, 768, h3,
                                                       gat3 + (size_t)l * 256 * 768,
                                                       nullptr, 256, m, nullptr);
        gat_kernel<<<BB, blk>>>(m, h, elog + (long)l * EE, dst,
                                gat_a + l * 768, gat_lng + l * HH, gat_lnb + l * HH, h3);
    }

    // global attention
    mma_gemm<0, true, false><<<g1, blk, MG_SMEM>>>(12, 768, h3, wq3, nullptr, 256, q, nullptr);
    mma_gemm<0, true, false><<<g1, blk, MG_SMEM>>>(12, 768, h3, wk3, nullptr, 256, k, nullptr);
    mma_gemm<0, true, false><<<g1, blk, MG_SMEM>>>(12, 768, h3, wv3, nullptr, 256, v, nullptr);
    attn_kernel<<<dim3(BB, HEADS), 64>>>(q, k, v, att);
    add_ln_kernel<<<NN, blk>>>(att, h, att_lng, att_lnb, 1e-6f, x, x3);

    // feed-forward
    mma_gemm<1, false, true><<<g2, blk, MG_SMEM>>>(12, 768, x3, w13, ff_b1, 512, nullptr, y13);
    mma_gemm<0, true, false><<<g1, blk, MG_SMEM>>>(24, 1536, y13, w23, ff_b2, 256, m, nullptr);
    add_ln_kernel<<<NN, blk>>>(x, m, ff_lng, ff_lnb, 1e-6f, h, h23);

    // gating readout
    mma_gemm<2, true, false><<<g1, blk, MG_SMEM>>>(12, 768, h23, gw13, gb1, 256, m, nullptr);
    rowdot_kernel<<<NN / 8, blk>>>(m, gW2, gb2, gs);
    readout_kernel<<<BB, blk>>>(h, gs, (float*)d_out);
}

// round 6
// speedup vs baseline: 1.8895x; 1.0698x over previous
#include <cuda_runtime.h>
#include <cuda_bf16.h>
#include <math.h>
#include <stdint.h>

// Problem constants
#define NN    16384
#define EE    131072
#define HH    256
#define LL    4
#define BB    256
#define NPG   64
#define DEG   8
#define HEADS 8
#define DK    32

// ---------------------------------------------------------------------------
// PTX helpers (baseline PTX only)
// ---------------------------------------------------------------------------
static __device__ __forceinline__ uint32_t su32(const void* p) {
    uint32_t a;
    asm("{ .reg .u64 t; cvta.to.shared.u64 t, %1; cvt.u32.u64 %0, t; }"
        : "=r"(a) : "l"(p));
    return a;
}
static __device__ __forceinline__ void cp16(uint32_t s, const void* g) {
    asm volatile("cp.async.cg.shared.global [%0], [%1], 16;" :: "r"(s), "l"(g));
}
#define CP_COMMIT() asm volatile("cp.async.commit_group;")
#define CP_WAIT(n)  asm volatile("cp.async.wait_group %0;" :: "n"(n))

static __device__ __forceinline__ void ldm4(uint32_t& r0, uint32_t& r1,
                                            uint32_t& r2, uint32_t& r3, uint32_t a) {
    asm volatile("ldmatrix.sync.aligned.m8n8.x4.shared.b16 {%0,%1,%2,%3}, [%4];"
                 : "=r"(r0), "=r"(r1), "=r"(r2), "=r"(r3) : "r"(a));
}
static __device__ __forceinline__ void mma16816(float* c, const uint32_t* a,
                                                const uint32_t* b) {
    asm volatile("mma.sync.aligned.m16n8k16.row.col.f32.bf16.bf16.f32 "
                 "{%0,%1,%2,%3}, {%4,%5,%6,%7}, {%8,%9}, {%0,%1,%2,%3};"
                 : "+f"(c[0]), "+f"(c[1]), "+f"(c[2]), "+f"(c[3])
                 : "r"(a[0]), "r"(a[1]), "r"(a[2]), "r"(a[3]),
                   "r"(b[0]), "r"(b[1]));
}

// ---------------------------------------------------------------------------
// scratch
// ---------------------------------------------------------------------------
__device__ float gbuf_h   [NN * HH];
__device__ float gbuf_m   [NN * HH];
__device__ float gbuf_qkv [NN * 768];
__device__ float gbuf_att [NN * HH];
__device__ float gbuf_x   [NN * HH];
__device__ float gbuf_elog[LL * EE];
__device__ float gbuf_we  [LL * 32];
__device__ float gbuf_ce  [LL];
__device__ float gbuf_gs  [NN];
__device__ float gbuf_aip [4 * NN];
__device__ float gbuf_ajp [4 * NN];

// bf16 triples: A'=[hi|hi|lo], B'=[hi|lo|hi] along K (row-major, 3K contiguous)
__device__ __nv_bfloat16 b_nf3  [NN * 192];
__device__ __nv_bfloat16 b_h3   [NN * 768];
__device__ __nv_bfloat16 b_x3   [NN * 768];
__device__ __nv_bfloat16 b_h23  [NN * 768];
__device__ __nv_bfloat16 b_y13  [NN * 1536];
__device__ __nv_bfloat16 b_wn3  [256 * 192];
__device__ __nv_bfloat16 b_gat3 [4 * 256 * 768];
__device__ __nv_bfloat16 b_wqkv3[768 * 768];
__device__ __nv_bfloat16 b_w13  [512 * 768];
__device__ __nv_bfloat16 b_w23  [256 * 1536];
__device__ __nv_bfloat16 b_gw13 [256 * 768];

static __device__ __forceinline__ void hilo(float v, __nv_bfloat16& h, __nv_bfloat16& l) {
    h = __float2bfloat16(v);
    l = __float2bfloat16(v - __bfloat162float(h));
}

// ---------------------------------------------------------------------------
// conversions
// ---------------------------------------------------------------------------
__global__ void to_tripleA(const float* __restrict__ src, int M, int K,
                           __nv_bfloat16* __restrict__ dst)
{
    long t = (long)blockIdx.x * 256 + threadIdx.x;
    if (t >= (long)M * K) return;
    int r = (int)(t / K), c = (int)(t % K);
    __nv_bfloat16 h, l;
    hilo(src[t], h, l);
    __nv_bfloat16* rp = dst + (size_t)r * 3 * K;
    rp[c] = h; rp[K + c] = h; rp[2 * K + c] = l;
}

struct WEnt { const float* src; __nv_bfloat16* dst; int K; int N; };
struct WTab { WEnt e[11]; };

__global__ void conv_weights(WTab tab)
{
    WEnt w = tab.e[blockIdx.y];
    int total = w.K * w.N;
    for (int t = blockIdx.x * 256 + threadIdx.x; t < total; t += gridDim.x * 256) {
        int k = t / w.N, n = t % w.N;
        __nv_bfloat16 h, l;
        hilo(w.src[t], h, l);
        __nv_bfloat16* rp = w.dst + (size_t)n * 3 * w.K;
        rp[k] = h; rp[w.K + k] = l; rp[2 * w.K + k] = h;
    }
}

// ---------------------------------------------------------------------------
// HMMA GEMM: C[M,NoutT] = A3[M,K3] @ B3[NoutT,K3]^T
// block 128x128, 8 warps (4Mx2N), warp 32x64, K-chunk 64, 3-stage cp.async.
// ACT: 0 none, 1 GELU, 2 ReLU. WF32: fp32 out. WTR: bf16 triple out.
// WAL: per-row alpha partial dots (GAT) into AIp/AJp slot (bx*2+wn).
// ---------------------------------------------------------------------------
#define MG_SMEM 98304

template<int ACT, bool WF32, bool WTR, bool WAL>
__global__ __launch_bounds__(256)
void mma_gemm(int KC, int K3,
              const __nv_bfloat16* __restrict__ A3,
              const __nv_bfloat16* __restrict__ B3,
              const float* __restrict__ bias, int NoutT,
              float* __restrict__ C,
              __nv_bfloat16* __restrict__ D3,
              const float* __restrict__ a_l,
              float* __restrict__ AIp, float* __restrict__ AJp)
{
    extern __shared__ char smem[];
    uint32_t sb = su32(smem);
    int tid = threadIdx.x, lane = tid & 31, wid = tid >> 5;
    int bx = blockIdx.x, by = blockIdx.y;
    const __nv_bfloat16* Abase = A3 + (size_t)by * 128 * K3;
    const __nv_bfloat16* Bbase = B3 + (size_t)bx * 128 * K3;

    float acc[2][8][4];
#pragma unroll
    for (int i = 0; i < 2; i++)
#pragma unroll
        for (int j = 0; j < 8; j++)
#pragma unroll
            for (int q = 0; q < 4; q++) acc[i][j][q] = 0.f;

    auto load_stage = [&](int c) {
        uint32_t st = sb + (uint32_t)(c % 3) * 32768u;
#pragma unroll
        for (int i = 0; i < 4; i++) {
            int idx = tid + i * 256;
            int row = idx >> 3, u = idx & 7;
            uint32_t soff = (uint32_t)row * 128 + (uint32_t)((u ^ (row & 7)) << 4);
            cp16(st + soff,         Abase + (size_t)row * K3 + c * 64 + u * 8);
            cp16(st + 16384 + soff, Bbase + (size_t)row * K3 + c * 64 + u * 8);
        }
    };

    load_stage(0); CP_COMMIT();
    if (KC > 1) load_stage(1);
    CP_COMMIT();

    int wm = wid & 3, wn = wid >> 2;
    int g = lane >> 3, r8 = lane & 7;
    int rsel = (g & 1) * 8 + r8;
    int usel = g >> 1;

    for (int c = 0; c < KC; c++) {
        CP_WAIT(1);
        __syncthreads();
        if (c + 2 < KC) load_stage(c + 2);
        CP_COMMIT();
        uint32_t as = sb + (uint32_t)(c % 3) * 32768u;
        uint32_t bs = as + 16384;
#pragma unroll
        for (int ks = 0; ks < 4; ks++) {
            int u = 2 * ks + usel;
            uint32_t a[2][4];
#pragma unroll
            for (int mt = 0; mt < 2; mt++) {
                int row = wm * 32 + mt * 16 + rsel;
                ldm4(a[mt][0], a[mt][1], a[mt][2], a[mt][3],
                     as + (uint32_t)row * 128 + (uint32_t)((u ^ (row & 7)) << 4));
            }
            uint32_t b[8][2];
#pragma unroll
            for (int np = 0; np < 4; np++) {
                int row = wn * 64 + np * 16 + rsel;
                uint32_t r0, r1, r2, r3;
                ldm4(r0, r1, r2, r3,
                     bs + (uint32_t)row * 128 + (uint32_t)((u ^ (row & 7)) << 4));
                b[2 * np][0] = r0; b[2 * np + 1][0] = r1;
                b[2 * np][1] = r2; b[2 * np + 1][1] = r3;
            }
#pragma unroll
            for (int mt = 0; mt < 2; mt++)
#pragma unroll
                for (int nt = 0; nt < 8; nt++)
                    mma16816(acc[mt][nt], a[mt], b[nt]);
        }
        __syncthreads();
    }

    // epilogue
    int gid = lane >> 2, qp = lane & 3;
    float sai[2][2], saj[2][2];
    if (WAL) {
#pragma unroll
        for (int i = 0; i < 2; i++)
#pragma unroll
            for (int j = 0; j < 2; j++) { sai[i][j] = 0.f; saj[i][j] = 0.f; }
    }
#pragma unroll
    for (int mt = 0; mt < 2; mt++) {
#pragma unroll
        for (int nt = 0; nt < 8; nt++) {
            int col = bx * 128 + wn * 64 + nt * 8 + qp * 2;
            float bb0 = bias ? bias[col] : 0.f;
            float bb1 = bias ? bias[col + 1] : 0.f;
#pragma unroll
            for (int hh2 = 0; hh2 < 2; hh2++) {
                long row = (long)by * 128 + wm * 32 + mt * 16 + gid + hh2 * 8;
                float v0 = acc[mt][nt][2 * hh2]     + bb0;
                float v1 = acc[mt][nt][2 * hh2 + 1] + bb1;
                if (ACT == 1) {
                    v0 = 0.5f * v0 * (1.0f + erff(v0 * 0.7071067811865475f));
                    v1 = 0.5f * v1 * (1.0f + erff(v1 * 0.7071067811865475f));
                }
                if (ACT == 2) { v0 = fmaxf(v0, 0.f); v1 = fmaxf(v1, 0.f); }
                if (WF32) {
                    float2 t2 = make_float2(v0, v1);
                    *reinterpret_cast<float2*>(&C[row * NoutT + col]) = t2;
                }
                if (WAL) {
                    sai[mt][hh2] += v0 * a_l[col] + v1 * a_l[col + 1];
                    saj[mt][hh2] += v0 * a_l[HH + col] + v1 * a_l[HH + col + 1];
                }
                if (WTR) {
                    __nv_bfloat16 h0, l0, h1, l1;
                    hilo(v0, h0, l0); hilo(v1, h1, l1);
                    __nv_bfloat162 hp, lp;
                    hp.x = h0; hp.y = h1; lp.x = l0; lp.y = l1;
                    __nv_bfloat16* rp = D3 + (size_t)row * 3 * NoutT;
                    *reinterpret_cast<__nv_bfloat162*>(&rp[col]) = hp;
                    *reinterpret_cast<__nv_bfloat162*>(&rp[NoutT + col]) = hp;
                    *reinterpret_cast<__nv_bfloat162*>(&rp[2 * NoutT + col]) = lp;
                }
            }
        }
    }
    if (WAL) {
        int slot = bx * 2 + wn;
#pragma unroll
        for (int mt = 0; mt < 2; mt++)
#pragma unroll
            for (int hh2 = 0; hh2 < 2; hh2++) {
                float si = sai[mt][hh2], sj = saj[mt][hh2];
                si += __shfl_xor_sync(0xFFFFFFFFu, si, 1);
                si += __shfl_xor_sync(0xFFFFFFFFu, si, 2);
                sj += __shfl_xor_sync(0xFFFFFFFFu, sj, 1);
                sj += __shfl_xor_sync(0xFFFFFFFFu, sj, 2);
                if (qp == 0) {
                    long row = (long)by * 128 + wm * 32 + mt * 16 + gid + hh2 * 8;
                    AIp[(size_t)slot * NN + row] = si;
                    AJp[(size_t)slot * NN + row] = sj;
                }
            }
    }
}

// ---------------------------------------------------------------------------
// fold edge weights + edge logits
// ---------------------------------------------------------------------------
__global__ void prep_kernel(const float* __restrict__ We, const float* __restrict__ be,
                            const float* __restrict__ gat_a,
                            float* __restrict__ we, float* __restrict__ ce)
{
    int tid = threadIdx.x;
    if (tid < 128) {
        int l = tid / 32, j = tid % 32;
        const float* ae = gat_a + l * 768 + 512;
        float s = 0.f;
        for (int c = 0; c < HH; c++) s += We[j * HH + c] * ae[c];
        we[tid] = s;
    } else if (tid < 132) {
        int l = tid - 128;
        const float* ae = gat_a + l * 768 + 512;
        float s = 0.f;
        for (int c = 0; c < HH; c++) s += be[c] * ae[c];
        ce[l] = s;
    }
}

__global__ void edge_logit_kernel(const float* __restrict__ ef,
                                  const float* __restrict__ we,
                                  const float* __restrict__ ce,
                                  float* __restrict__ elog)
{
    __shared__ float ws[128];
    __shared__ float cs[4];
    int tid = threadIdx.x;
    if (tid < 128) ws[tid] = we[tid];
    if (tid < 4)   cs[tid] = ce[tid];
    __syncthreads();
    int e = blockIdx.x * 256 + tid;
    float f[32];
    const float4* efp = reinterpret_cast<const float4*>(ef + (long)e * 32);
#pragma unroll
    for (int t = 0; t < 8; t++) {
        float4 x = efp[t];
        f[4*t+0] = x.x; f[4*t+1] = x.y; f[4*t+2] = x.z; f[4*t+3] = x.w;
    }
#pragma unroll
    for (int l = 0; l < LL; l++) {
        float s = cs[l];
#pragma unroll
        for (int j = 0; j < 32; j++) s += f[j] * ws[l * 32 + j];
        elog[l * EE + e] = s;
    }
}

// ---------------------------------------------------------------------------
// GAT layer (alphas precomputed by GEMM epilogue)
// ---------------------------------------------------------------------------
__global__ __launch_bounds__(256)
void gat_kernel(const float* __restrict__ m, float* __restrict__ h,
                const float* __restrict__ elog_l, const int* __restrict__ dst,
                const float* __restrict__ aip, const float* __restrict__ ajp,
                const float* __restrict__ lng, const float* __restrict__ lnb,
                __nv_bfloat16* __restrict__ h3)
{
    int g = blockIdx.x;
    int tid = threadIdx.x;
    int w = tid >> 5, lane = tid & 31;
    __shared__ float ai[NPG], aj[NPG];
    __shared__ float s_attn[8][8];
    __shared__ int   s_dl[8][8];

    if (tid < NPG) {
        int node = g * NPG + tid;
        ai[tid] = aip[node] + aip[NN + node] + aip[2 * NN + node] + aip[3 * NN + node];
        aj[tid] = ajp[node] + ajp[NN + node] + ajp[2 * NN + node] + ajp[3 * NN + node];
    }
    __syncthreads();

    for (int n = w; n < NPG; n += 8) {
        int node = g * NPG + n;
        float logit = -1e30f;
        int dl = 0;
        if (lane < DEG) {
            int e = node * DEG + lane;
            dl = dst[e] - g * NPG;
            float lg = ai[n] + aj[dl] + elog_l[e];
            logit = (lg >= 0.f) ? lg : 0.01f * lg;
        }
        float mx = logit;
#pragma unroll
        for (int o = 4; o; o >>= 1) mx = fmaxf(mx, __shfl_xor_sync(0xFFFFFFFFu, mx, o));
        float ex = (lane < DEG) ? expf(logit - mx) : 0.f;
        float sm = ex;
#pragma unroll
        for (int o = 4; o; o >>= 1) sm += __shfl_xor_sync(0xFFFFFFFFu, sm, o);
        if (lane < DEG) { s_attn[w][lane] = ex / sm; s_dl[w][lane] = dl; }
        __syncwarp();

        float acc[8];
#pragma unroll
        for (int jj = 0; jj < 8; jj++) acc[jj] = 0.f;
        long gbase = (long)g * NPG * HH;
#pragma unroll
        for (int kk = 0; kk < DEG; kk++) {
            float at = s_attn[w][kk];
            const float* mr = m + gbase + (long)s_dl[w][kk] * HH;
#pragma unroll
            for (int jj = 0; jj < 8; jj++)
                acc[jj] += at * mr[lane + 32 * jj];
        }
        float* hr = h + (long)node * HH;
        float s = 0.f, s2 = 0.f;
#pragma unroll
        for (int jj = 0; jj < 8; jj++) {
            float vv = acc[jj] + hr[lane + 32 * jj];
            acc[jj] = vv;
            s += vv; s2 += vv * vv;
        }
#pragma unroll
        for (int o = 16; o; o >>= 1) {
            s  += __shfl_xor_sync(0xFFFFFFFFu, s,  o);
            s2 += __shfl_xor_sync(0xFFFFFFFFu, s2, o);
        }
        float mean = s * (1.0f / HH);
        float var  = s2 * (1.0f / HH) - mean * mean;
        float inv  = rsqrtf(var + 1e-5f);
        __nv_bfloat16* rp = h3 + (size_t)node * 768;
#pragma unroll
        for (int jj = 0; jj < 8; jj++) {
            int c = lane + 32 * jj;
            float val = (acc[jj] - mean) * inv * lng[c] + lnb[c];
            hr[c] = val;
            __nv_bfloat16 hb, lb;
            hilo(val, hb, lb);
            rp[c] = hb; rp[256 + c] = hb; rp[512 + c] = lb;
        }
        __syncwarp();
    }
}

// ---------------------------------------------------------------------------
// global attention (qkv fused layout: [NN][q 256 | k 256 | v 256])
// ---------------------------------------------------------------------------
__global__ __launch_bounds__(64)
void attn_kernel(const float* __restrict__ qkv, float* __restrict__ o)
{
    int g = blockIdx.x, hd = blockIdx.y;
    int i = threadIdx.x;
    __shared__ float ks[NPG][DK];
    __shared__ float vs[NPG][DK];
    __shared__ float sc[NPG][NPG + 1];
    long nbase = (long)g * NPG;
    for (int t = i; t < NPG * DK; t += 64) {
        int r = t / DK, c = t % DK;
        long rb = (nbase + r) * 768 + hd * DK;
        ks[r][c] = qkv[rb + 256 + c];
        vs[r][c] = qkv[rb + 512 + c];
    }
    __syncthreads();
    float qr[DK];
    long qb = (nbase + i) * 768 + hd * DK;
#pragma unroll
    for (int d = 0; d < DK; d++) qr[d] = qkv[qb + d];
    float mx = -1e30f;
    for (int j = 0; j < NPG; j++) {
        float s = 0.f;
#pragma unroll
        for (int d = 0; d < DK; d++) s += qr[d] * ks[j][d];
        s *= 0.1767766952966369f;
        sc[i][j] = s;
        mx = fmaxf(mx, s);
    }
    float sm = 0.f;
    for (int j = 0; j < NPG; j++) {
        float e = expf(sc[i][j] - mx);
        sc[i][j] = e;
        sm += e;
    }
    float inv = 1.0f / sm;
    long ob = (nbase + i) * HH + hd * DK;
#pragma unroll 4
    for (int d = 0; d < DK; d++) {
        float acc = 0.f;
        for (int j = 0; j < NPG; j++) acc += sc[i][j] * vs[j][d];
        o[ob + d] = acc * inv;
    }
}

// ---------------------------------------------------------------------------
// out = LN(a + b) fp32 + optional bf16 triple
// ---------------------------------------------------------------------------
__global__ __launch_bounds__(256)
void add_ln_kernel(const float* __restrict__ a, const float* __restrict__ b,
                   const float* __restrict__ gamma, const float* __restrict__ beta,
                   float eps, float* __restrict__ out,
                   __nv_bfloat16* __restrict__ t3)
{
    long r = blockIdx.x;
    int c = threadIdx.x;
    int w = c >> 5, lane = c & 31;
    float vv = a[r * HH + c] + b[r * HH + c];
    float s = vv, s2 = vv * vv;
#pragma unroll
    for (int o = 16; o; o >>= 1) {
        s  += __shfl_xor_sync(0xFFFFFFFFu, s,  o);
        s2 += __shfl_xor_sync(0xFFFFFFFFu, s2, o);
    }
    __shared__ float rs[8], rs2[8];
    if (lane == 0) { rs[w] = s; rs2[w] = s2; }
    __syncthreads();
    float ts = 0.f, ts2 = 0.f;
#pragma unroll
    for (int i = 0; i < 8; i++) { ts += rs[i]; ts2 += rs2[i]; }
    float mean = ts * (1.0f / HH);
    float var  = ts2 * (1.0f / HH) - mean * mean;
    float inv  = rsqrtf(var + eps);
    float val = (vv - mean) * inv * gamma[c] + beta[c];
    out[r * HH + c] = val;
    if (t3) {
        __nv_bfloat16 hb, lb;
        hilo(val, hb, lb);
        __nv_bfloat16* rp = t3 + (size_t)r * 768;
        rp[c] = hb; rp[256 + c] = hb; rp[512 + c] = lb;
    }
}

// ---------------------------------------------------------------------------
// gating scalar + readout
// ---------------------------------------------------------------------------
__global__ __launch_bounds__(256)
void rowdot_kernel(const float* __restrict__ t, const float* __restrict__ w2,
                   const float* __restrict__ b2, float* __restrict__ gs)
{
    int w = threadIdx.x >> 5, lane = threadIdx.x & 31;
    long r = (long)blockIdx.x * 8 + w;
    float s = 0.f;
    for (int c = lane; c < HH; c += 32) s += t[r * HH + c] * w2[c];
#pragma unroll
    for (int o = 16; o; o >>= 1) s += __shfl_xor_sync(0xFFFFFFFFu, s, o);
    if (lane == 0) gs[r] = s + b2[0];
}

__global__ __launch_bounds__(256)
void readout_kernel(const float* __restrict__ x, const float* __restrict__ gs,
                    float* __restrict__ out)
{
    int g = blockIdx.x, tid = threadIdx.x;
    __shared__ float p[NPG];
    if (tid < NPG) p[tid] = gs[g * NPG + tid];
    __syncthreads();
    if (tid == 0) {
        float mx = -1e30f;
        for (int i = 0; i < NPG; i++) mx = fmaxf(mx, p[i]);
        float sm = 0.f;
        for (int i = 0; i < NPG; i++) { p[i] = expf(p[i] - mx); sm += p[i]; }
        float inv = 1.0f / sm;
        for (int i = 0; i < NPG; i++) p[i] *= inv;
    }
    __syncthreads();
    float acc = 0.f;
    long gbase = (long)g * NPG * HH;
    for (int n = 0; n < NPG; n++)
        acc += p[n] * x[gbase + (long)n * HH + tid];
    out[(long)g * HH + tid] = acc;
}

// ---------------------------------------------------------------------------
// launch
// ---------------------------------------------------------------------------
extern "C" void kernel_launch(void* const* d_in, const int* in_sizes, int n_in,
                              void* d_out, int out_size)
{
    const float* node_feats = (const float*)d_in[0];
    const float* edge_feats = (const float*)d_in[1];
    const int*   dst        = (const int*)  d_in[3];
    const float* Wn      = (const float*)d_in[4];
    const float* bn      = (const float*)d_in[5];
    const float* We      = (const float*)d_in[6];
    const float* be      = (const float*)d_in[7];
    const float* gat_W   = (const float*)d_in[8];
    const float* gat_a   = (const float*)d_in[9];
    const float* gat_lng = (const float*)d_in[10];
    const float* gat_lnb = (const float*)d_in[11];
    const float* Wq      = (const float*)d_in[12];
    const float* Wk      = (const float*)d_in[13];
    const float* Wv      = (const float*)d_in[14];
    const float* att_lng = (const float*)d_in[15];
    const float* att_lnb = (const float*)d_in[16];
    const float* ff_W1   = (const float*)d_in[17];
    const float* ff_b1   = (const float*)d_in[18];
    const float* ff_W2   = (const float*)d_in[19];
    const float* ff_b2   = (const float*)d_in[20];
    const float* ff_lng  = (const float*)d_in[21];
    const float* ff_lnb  = (const float*)d_in[22];
    const float* gW1     = (const float*)d_in[23];
    const float* gb1     = (const float*)d_in[24];
    const float* gW2     = (const float*)d_in[25];
    const float* gb2     = (const float*)d_in[26];

    float *h, *m, *qkv, *att, *x, *elog, *we, *ce, *gs, *aip, *ajp;
    cudaGetSymbolAddress((void**)&h,    gbuf_h);
    cudaGetSymbolAddress((void**)&m,    gbuf_m);
    cudaGetSymbolAddress((void**)&qkv,  gbuf_qkv);
    cudaGetSymbolAddress((void**)&att,  gbuf_att);
    cudaGetSymbolAddress((void**)&x,    gbuf_x);
    cudaGetSymbolAddress((void**)&elog, gbuf_elog);
    cudaGetSymbolAddress((void**)&we,   gbuf_we);
    cudaGetSymbolAddress((void**)&ce,   gbuf_ce);
    cudaGetSymbolAddress((void**)&gs,   gbuf_gs);
    cudaGetSymbolAddress((void**)&aip,  gbuf_aip);
    cudaGetSymbolAddress((void**)&ajp,  gbuf_ajp);

    __nv_bfloat16 *nf3, *h3, *x3, *h23, *y13;
    __nv_bfloat16 *wn3, *gat3, *wqkv3, *w13, *w23, *gw13;
    cudaGetSymbolAddress((void**)&nf3,   b_nf3);
    cudaGetSymbolAddress((void**)&h3,    b_h3);
    cudaGetSymbolAddress((void**)&x3,    b_x3);
    cudaGetSymbolAddress((void**)&h23,   b_h23);
    cudaGetSymbolAddress((void**)&y13,   b_y13);
    cudaGetSymbolAddress((void**)&wn3,   b_wn3);
    cudaGetSymbolAddress((void**)&gat3,  b_gat3);
    cudaGetSymbolAddress((void**)&wqkv3, b_wqkv3);
    cudaGetSymbolAddress((void**)&w13,   b_w13);
    cudaGetSymbolAddress((void**)&w23,   b_w23);
    cudaGetSymbolAddress((void**)&gw13,  b_gw13);

    cudaFuncSetAttribute((const void*)mma_gemm<0, true,  true,  false>, cudaFuncAttributeMaxDynamicSharedMemorySize, MG_SMEM);
    cudaFuncSetAttribute((const void*)mma_gemm<0, true,  false, true >, cudaFuncAttributeMaxDynamicSharedMemorySize, MG_SMEM);
    cudaFuncSetAttribute((const void*)mma_gemm<0, true,  false, false>, cudaFuncAttributeMaxDynamicSharedMemorySize, MG_SMEM);
    cudaFuncSetAttribute((const void*)mma_gemm<1, false, true,  false>, cudaFuncAttributeMaxDynamicSharedMemorySize, MG_SMEM);
    cudaFuncSetAttribute((const void*)mma_gemm<2, true,  false, false>, cudaFuncAttributeMaxDynamicSharedMemorySize, MG_SMEM);

    dim3 blk(256);

    prep_kernel<<<1, 160>>>(We, be, gat_a, we, ce);
    edge_logit_kernel<<<EE / 256, blk>>>(edge_feats, we, ce, elog);

    // fused weight conversions (1 launch)
    WTab tab;
    tab.e[0]  = { Wn,                       wn3,               64,  256 };
    tab.e[1]  = { gat_W + 0 * 65536,        gat3 + 0 * 196608, 256, 256 };
    tab.e[2]  = { gat_W + 1 * 65536,        gat3 + 1 * 196608, 256, 256 };
    tab.e[3]  = { gat_W + 2 * 65536,        gat3 + 2 * 196608, 256, 256 };
    tab.e[4]  = { gat_W + 3 * 65536,        gat3 + 3 * 196608, 256, 256 };
    tab.e[5]  = { Wq,                       wqkv3,             256, 256 };
    tab.e[6]  = { Wk,                       wqkv3 + 256 * 768, 256, 256 };
    tab.e[7]  = { Wv,                       wqkv3 + 512 * 768, 256, 256 };
    tab.e[8]  = { ff_W1,                    w13,               256, 512 };
    tab.e[9]  = { ff_W2,                    w23,               512, 256 };
    tab.e[10] = { gW1,                      gw13,              256, 256 };
    conv_weights<<<dim3(64, 11), blk>>>(tab);
    to_tripleA<<<(NN * 64 + 255) / 256, blk>>>(node_feats, NN, 64, nf3);

    dim3 g1(2, NN / 128);    // Nout 256
    dim3 g2(4, NN / 128);    // Nout 512
    dim3 g3(6, NN / 128);    // Nout 768 (QKV)

    // input projection
    mma_gemm<0, true, true, false><<<g1, blk, MG_SMEM>>>(3, 192, nf3, wn3, bn, 256,
                                                         h, h3, nullptr, nullptr, nullptr);
    // GAT layers
    for (int l = 0; l < LL; l++) {
        mma_gemm<0, true, false, true><<<g1, blk, MG_SMEM>>>(12, 768, h3,
            gat3 + (size_t)l * 196608, nullptr, 256, m, nullptr,
            gat_a + l * 768, aip, ajp);
        gat_kernel<<<BB, blk>>>(m, h, elog + (long)l * EE, dst, aip, ajp,
                                gat_lng + l * HH, gat_lnb + l * HH, h3);
    }

    // global attention (fused QKV)
    mma_gemm<0, true, false, false><<<g3, blk, MG_SMEM>>>(12, 768, h3, wqkv3,
        nullptr, 768, qkv, nullptr, nullptr, nullptr, nullptr);
    attn_kernel<<<dim3(BB, HEADS), 64>>>(qkv, att);
    add_ln_kernel<<<NN, blk>>>(att, h, att_lng, att_lnb, 1e-6f, x, x3);

    // feed-forward
    mma_gemm<1, false, true, false><<<g2, blk, MG_SMEM>>>(12, 768, x3, w13, ff_b1, 512,
                                                          nullptr, y13, nullptr, nullptr, nullptr);
    mma_gemm<0, true, false, false><<<g1, blk, MG_SMEM>>>(24, 1536, y13, w23, ff_b2, 256,
                                                          m, nullptr, nullptr, nullptr, nullptr);
    add_ln_kernel<<<NN, blk>>>(x, m, ff_lng, ff_lnb, 1e-6f, h, h23);

    // gating readout
    mma_gemm<2, true, false, false><<<g1, blk, MG_SMEM>>>(12, 768, h23, gw13, gb1, 256,
                                                          m, nullptr, nullptr, nullptr, nullptr);
    rowdot_kernel<<<NN / 8, blk>>>(m, gW2, gb2, gs);
    readout_kernel<<<BB, blk>>>(h, gs, (float*)d_out);
}